// round 4
// baseline (speedup 1.0000x reference)
#include <cuda_runtime.h>
#include <math.h>

#define NT 365
#define NS 1024
#define NH 64
#define NG 32
#define NW 514          // NH*8 + 2
#define PITCH 17        // partial-sum row pitch (conflict-free)

// Scratch for gate pre-activations w[s][j]
__device__ float g_w[NS * NW];

__device__ __forceinline__ float sigm(float x) { return 1.0f / (1.0f + expf(-x)); }

// ---------------------------------------------------------------------------
// Gates: w = xc @ fc_w.T + fc_b.  128 blocks x 256 threads, 8 sites/block.
// xc in registers; fc_w staged in padded shared (pitch 33, conflict-free).
// ---------------------------------------------------------------------------
__global__ void __launch_bounds__(256)
gates_kernel(const float* __restrict__ xc,
             const float* __restrict__ fc_w,
             const float* __restrict__ fc_b) {
    __shared__ float sh_w[258 * 33];

    const int tid  = threadIdx.x;
    const int lane = tid & 31;
    const int si   = tid >> 5;
    const int s    = blockIdx.x * 8 + si;

    float xr[32];
    {
        const float4* xc4 = reinterpret_cast<const float4*>(xc + s * NG);
        #pragma unroll
        for (int q = 0; q < 8; ++q) {
            float4 v = xc4[q];
            xr[q * 4 + 0] = v.x; xr[q * 4 + 1] = v.y;
            xr[q * 4 + 2] = v.z; xr[q * 4 + 3] = v.w;
        }
    }

    #pragma unroll
    for (int pass = 0; pass < 2; ++pass) {
        const int rbase = pass ? 256 : 0;
        const int rcnt  = pass ? 258 : 256;
        __syncthreads();
        for (int i = tid; i < rcnt * NG; i += 256) {
            int r = i >> 5, k = i & 31;
            sh_w[r * 33 + k] = fc_w[(rbase + r) * NG + k];
        }
        __syncthreads();
        const int clo = pass ? 8 : 0;
        const int chi = pass ? 17 : 8;
        for (int c = clo; c < chi; ++c) {
            int j = lane + 32 * c;
            if (j < NW) {
                const float* row = sh_w + (j - rbase) * 33;
                float acc = 0.0f;
                #pragma unroll
                for (int k = 0; k < NG; ++k)
                    acc += xr[k] * row[k];
                g_w[s * NW + j] = acc + fc_b[j];
            }
        }
    }
}

// ---------------------------------------------------------------------------
// Scan: ONE SITE = TWO WARPS (32 h per warp, 1 unit per lane).
// 1024 blocks x 64 threads -> 2048 warps (3.46/SMSP) for latency hiding.
// In-loop: LDS.128 forcing + ~20 math ops + 2 shfl + STS of 8 partials.
// Post-pass combines 16 partials per t (+qb) and writes out.
// ---------------------------------------------------------------------------
__global__ void __launch_bounds__(64)
scan_kernel(const float* __restrict__ x, float* __restrict__ out) {
    __shared__ float4 sForc[NT];            // 5840 B
    __shared__ float  sPart[NT * PITCH];    // 24820 B
    __shared__ float  sMax[2], sSum[2];

    const int tid  = threadIdx.x;
    const int warp = tid >> 5;
    const int lane = tid & 31;
    const int s    = blockIdx.x;

    // ---- stage forcing + rain/snow partition ----
    const float4* x4 = reinterpret_cast<const float4*>(x);
    for (int t = tid; t < NT; t += 64) {
        float4 xi = x4[t * NS + s];
        float P = xi.x, E = xi.y, T1 = xi.z, T2 = xi.w;
        float Ta = (T1 + T2) * 0.5f;
        bool valid  = (T1 < 0.0f) && (T2 > 0.0f);
        float denom = valid ? (T2 - T1) : 1.0f;
        float ratio = valid ? (T1 + T2) / denom : 0.0f;
        ratio = fminf(fmaxf(ratio, -0.999999f), 0.999999f);
        float rP = 1.0f - acosf(ratio) / 3.1415f;
        if (T1 >= 0.0f) rP = 1.0f;
        if (T2 <= 0.0f) rP = 0.0f;
        float4 o;
        o.x = (1.0f - rP) * P;   // Ps
        o.y = rP * P;            // Pl
        o.z = Ta;
        o.w = E;
        sForc[t] = o;
    }

    // ---- per-h gate constants (h = warp*32 + lane) ----
    const float* wrow = g_w + s * NW;
    const int h = warp * 32 + lane;
    float w0 = wrow[0 * NH + h];
    float w1 = wrow[1 * NH + h];
    float w2 = wrow[2 * NH + h];
    float w3 = wrow[3 * NH + h];
    float w4 = wrow[4 * NH + h];
    float w5 = wrow[5 * NH + h];
    float w6 = wrow[6 * NH + h];
    float w7 = wrow[7 * NH + h];
    float gm   = expf(w0) + 1.0f;
    float nge  = -2.0f * sigm(w1);
    float go   = sigm(w2);
    float gl   = expf(2.0f * w3);
    float araw = w4;
    float gb   = sigm(w5);
    float kb   = sigm(w6) * 0.1f;
    float gi   = sigm(w7);
    float kb1  = 1.0f - kb;

    // ---- softmax over 64 h across the 2 warps ----
    float m = araw;
    #pragma unroll
    for (int o = 16; o; o >>= 1) m = fmaxf(m, __shfl_xor_sync(0xffffffffu, m, o));
    if (lane == 0) sMax[warp] = m;
    __syncthreads();
    m = fmaxf(sMax[0], sMax[1]);
    float e = expf(araw - m);
    float ssum = e;
    #pragma unroll
    for (int o = 16; o; o >>= 1) ssum += __shfl_xor_sync(0xffffffffu, ssum, o);
    if (lane == 0) sSum[warp] = ssum;
    __syncthreads();
    float ga = e / (sSum[0] + sSum[1]);

    float chc  = go * (1.0f - gb) * ga - ga;   // coeff of Hc in y
    float cg   = kb * ga;                      // coeff of g2 in y
    float gogb = go * gb;

    // ---- sequential scan: 1 state-set per lane ----
    float S0 = 0.0f, H0 = 0.0f, G0 = 0.0f;

    #pragma unroll 4
    for (int t = 0; t < NT; ++t) {
        float4 f = sForc[t];                   // broadcast LDS.128
        float mt  = fmaxf(f.z * gm, 0.0f);
        float Sm  = fminf(S0, mt);
        float At  = fmaf(f.w, nge, f.y * gi);  // Pl*gi - E*ge
        float H   = fmaxf(H0 + Sm + At, 0.0f);
        float Hc  = fminf(H, gl);
        float t1  = fmaf(-go, Hc, H);          // H - Hc*go
        float g2  = fmaf(Hc, gogb, G0);
        H0 = fminf(t1, gl);
        G0 = g2 * kb1;
        S0 = (S0 - Sm) + f.x;
        float y = H * ga;
        y = fmaf(Hc, chc, y);
        y = fmaf(g2, cg, y);
        y += __shfl_xor_sync(0xffffffffu, y, 16);
        y += __shfl_xor_sync(0xffffffffu, y, 8);
        if (lane < 8) sPart[t * PITCH + warp * 8 + lane] = y;   // issue-only STS
    }

    __syncthreads();

    // ---- post-pass: sum 16 partials per t (+qb), write out ----
    const float qb = fmaxf(wrow[NW - 1], 0.0f) * (1.0f / 64.0f);
    for (int t = tid; t < NT; t += 64) {
        const float* row = sPart + t * PITCH;
        float acc = qb;
        #pragma unroll
        for (int k = 0; k < 16; ++k) acc += row[k];
        out[t * NS + s] = acc;
    }
}

// ---------------------------------------------------------------------------
extern "C" void kernel_launch(void* const* d_in, const int* in_sizes, int n_in,
                              void* d_out, int out_size) {
    const float* x    = (const float*)d_in[0];   // [NT, NS, 4]
    const float* xc   = (const float*)d_in[1];   // [NS, NG]
    const float* fc_w = (const float*)d_in[2];   // [NW, NG]
    const float* fc_b = (const float*)d_in[3];   // [NW]
    float* out = (float*)d_out;                  // [NT, NS]

    gates_kernel<<<NS / 8, 256>>>(xc, fc_w, fc_b);
    scan_kernel<<<NS, 64>>>(x, out);
}

// round 5
// speedup vs baseline: 1.0287x; 1.0287x over previous
#include <cuda_runtime.h>
#include <math.h>

#define NT 365
#define NS 1024
#define NH 64
#define NG 32
#define NW 514          // NH*8 + 2
#define PITCH 17        // partial-sum row pitch (conflict-free)

__device__ __forceinline__ float sigm(float x) { return 1.0f / (1.0f + expf(-x)); }

// ---------------------------------------------------------------------------
// Fused kernel: one block (64 threads = 2 warps) per site.
//  Prologue: stage forcing (+acos partition), compute this site's 514 gate
//            pre-activations inline (fc_w is L2-hot across blocks), softmax.
//  Loop:     branch-free: LDS.128 + ~17 math + 2 shfl + 1 unconditional STS.
//  Post:     reduce 16 partials per t (+qb), coalesced STG.
// ---------------------------------------------------------------------------
__global__ void __launch_bounds__(64)
waternet_kernel(const float* __restrict__ x,
                const float* __restrict__ xc,
                const float* __restrict__ fc_w,
                const float* __restrict__ fc_b,
                float* __restrict__ out) {
    __shared__ float4 sForc[NT];            // 5840 B
    __shared__ float  sPart[NT * PITCH];    // 24820 B
    __shared__ float  sXc[NG];
    __shared__ float  sMax[2], sSum[2], sQb;

    const int tid  = threadIdx.x;
    const int warp = tid >> 5;
    const int lane = tid & 31;
    const int s    = blockIdx.x;

    // ---- stage xc for this site ----
    if (tid < NG) sXc[tid] = xc[s * NG + tid];

    // ---- stage forcing + rain/snow partition ----
    const float4* x4 = reinterpret_cast<const float4*>(x);
    for (int t = tid; t < NT; t += 64) {
        float4 xi = x4[t * NS + s];
        float P = xi.x, E = xi.y, T1 = xi.z, T2 = xi.w;
        float Ta = (T1 + T2) * 0.5f;
        bool valid  = (T1 < 0.0f) && (T2 > 0.0f);
        float denom = valid ? (T2 - T1) : 1.0f;
        float ratio = valid ? (T1 + T2) / denom : 0.0f;
        ratio = fminf(fmaxf(ratio, -0.999999f), 0.999999f);
        float rP = 1.0f - acosf(ratio) / 3.1415f;
        if (T1 >= 0.0f) rP = 1.0f;
        if (T2 <= 0.0f) rP = 0.0f;
        float4 o;
        o.x = (1.0f - rP) * P;   // Ps
        o.y = rP * P;            // Pl
        o.z = Ta;
        o.w = E;
        sForc[t] = o;
    }
    __syncthreads();

    // ---- inline gates: thread h computes w[c*64+h] for c = 0..7 ----
    const int h = tid;                       // 0..63
    float wv[8];
    #pragma unroll
    for (int c = 0; c < 8; ++c) {
        const float4* row = reinterpret_cast<const float4*>(fc_w + (c * NH + h) * NG);
        float acc = 0.0f;
        #pragma unroll
        for (int q = 0; q < 8; ++q) {
            float4 v = row[q];
            acc += sXc[q * 4 + 0] * v.x + sXc[q * 4 + 1] * v.y
                 + sXc[q * 4 + 2] * v.z + sXc[q * 4 + 3] * v.w;
        }
        wv[c] = acc + fc_b[c * NH + h];
    }
    if (tid == 0) {
        const float4* row = reinterpret_cast<const float4*>(fc_w + (NW - 1) * NG);
        float acc = 0.0f;
        #pragma unroll
        for (int q = 0; q < 8; ++q) {
            float4 v = row[q];
            acc += sXc[q * 4 + 0] * v.x + sXc[q * 4 + 1] * v.y
                 + sXc[q * 4 + 2] * v.z + sXc[q * 4 + 3] * v.w;
        }
        sQb = fmaxf(acc + fc_b[NW - 1], 0.0f) * (1.0f / 64.0f);
    }

    float gm   = expf(wv[0]) + 1.0f;
    float nge  = -2.0f * sigm(wv[1]);
    float go   = sigm(wv[2]);
    float gl   = expf(2.0f * wv[3]);
    float araw = wv[4];
    float gb   = sigm(wv[5]);
    float kb   = sigm(wv[6]) * 0.1f;
    float gi   = sigm(wv[7]);
    float kb1  = 1.0f - kb;

    // ---- softmax over 64 h across the 2 warps ----
    float m = araw;
    #pragma unroll
    for (int o = 16; o; o >>= 1) m = fmaxf(m, __shfl_xor_sync(0xffffffffu, m, o));
    if (lane == 0) sMax[warp] = m;
    __syncthreads();
    m = fmaxf(sMax[0], sMax[1]);
    float e = expf(araw - m);
    float ssum = e;
    #pragma unroll
    for (int o = 16; o; o >>= 1) ssum += __shfl_xor_sync(0xffffffffu, ssum, o);
    if (lane == 0) sSum[warp] = ssum;
    __syncthreads();
    float ga = e / (sSum[0] + sSum[1]);

    float chc  = go * (1.0f - gb) * ga - ga;   // coeff of Hc in y
    float cg   = kb * ga;                      // coeff of g2 in y
    float gogb = go * gb;

    // ---- sequential scan: branch-free body ----
    float S0 = 0.0f, H0 = 0.0f, G0 = 0.0f;
    const int pbase = (warp << 3) + (lane & 7);   // collapsed store slot

    #pragma unroll 4
    for (int t = 0; t < NT; ++t) {
        float4 f = sForc[t];                   // broadcast LDS.128
        float mt  = fmaxf(f.z * gm, 0.0f);
        float Sm  = fminf(S0, mt);
        float At  = fmaf(f.w, nge, f.y * gi);  // Pl*gi - E*ge
        float H   = fmaxf(H0 + Sm + At, 0.0f);
        float Hc  = fminf(H, gl);
        float t1  = fmaf(-go, Hc, H);          // H - Hc*go
        float g2  = fmaf(Hc, gogb, G0);
        H0 = fminf(t1, gl);
        G0 = g2 * kb1;
        S0 = (S0 - Sm) + f.x;
        float y = H * ga;
        y = fmaf(Hc, chc, y);
        y = fmaf(g2, cg, y);
        y += __shfl_xor_sync(0xffffffffu, y, 16);
        y += __shfl_xor_sync(0xffffffffu, y, 8);
        // lanes {l, l+8, l+16, l+24} hold identical sums -> same-addr same-data
        // stores collapse: unconditional, NO branch in the loop body.
        sPart[t * PITCH + pbase] = y;
    }

    __syncthreads();

    // ---- post-pass: sum 16 partials per t (+qb), write out ----
    const float qb = sQb;
    for (int t = tid; t < NT; t += 64) {
        const float* row = sPart + t * PITCH;
        float acc = qb;
        #pragma unroll
        for (int k = 0; k < 16; ++k) acc += row[k];
        out[t * NS + s] = acc;
    }
}

// ---------------------------------------------------------------------------
extern "C" void kernel_launch(void* const* d_in, const int* in_sizes, int n_in,
                              void* d_out, int out_size) {
    const float* x    = (const float*)d_in[0];   // [NT, NS, 4]
    const float* xc   = (const float*)d_in[1];   // [NS, NG]
    const float* fc_w = (const float*)d_in[2];   // [NW, NG]
    const float* fc_b = (const float*)d_in[3];   // [NW]
    float* out = (float*)d_out;                  // [NT, NS]

    waternet_kernel<<<NS, 64>>>(x, xc, fc_w, fc_b, out);
}

// round 6
// speedup vs baseline: 1.4425x; 1.4023x over previous
#include <cuda_runtime.h>
#include <math.h>

#define NT 365
#define NS 1024
#define NH 64
#define NG 32
#define NW 514          // NH*8 + 2
#define PITCH 17        // partial-sum row pitch (conflict-free post-pass)

__device__ __forceinline__ float sigm(float x) { return 1.0f / (1.0f + expf(-x)); }

// ---------------------------------------------------------------------------
// Fused kernel: one block (64 threads = 2 warps) per site.
//  Prologue: stage forcing (+acos), COALESCED gate GEMV (warp-cooperative:
//            1 LDG.128 = 4 consecutive fc_w rows, dot4 + 3-shfl butterfly),
//            softmax.  Scratch (sW/xc/max/sum) overlaid on sPart.
//  Loop:     prefetched LDS.128, ~20 math, shfl16+shfl8, collapsed STS(8),
//            unroll 2 so var-lat ops fit the 6 scoreboard slots.
//  Post:     sum 16 partials per t (+qb), coalesced STG.
// ---------------------------------------------------------------------------
__global__ void __launch_bounds__(64)
waternet_kernel(const float* __restrict__ x,
                const float* __restrict__ xc,
                const float* __restrict__ fc_w,
                const float* __restrict__ fc_b,
                float* __restrict__ out) {
    __shared__ float4 sForc[NT + 1];        // 5856 B (padded for prefetch)
    __shared__ float  sPart[NT * PITCH];    // 24820 B (overlaid scratch below)
    __shared__ float  sQb;                  // survives the loop (post-pass)

    // Overlays inside sPart (all consumed before first loop STS):
    float*  sW   = sPart;                                   // [8*64]
    float4* sXc4 = reinterpret_cast<float4*>(sPart + 512);  // [8], 16B aligned
    float*  sMax = sPart + 544;                             // [2]
    float*  sSum = sPart + 546;                             // [2]

    const int tid  = threadIdx.x;
    const int warp = tid >> 5;
    const int lane = tid & 31;
    const int s    = blockIdx.x;

    // ---- stage xc (as float4) ----
    if (tid < 8) sXc4[tid] = reinterpret_cast<const float4*>(xc + s * NG)[tid];

    // ---- stage forcing + rain/snow partition ----
    const float4* x4 = reinterpret_cast<const float4*>(x);
    for (int t = tid; t < NT; t += 64) {
        float4 xi = x4[t * NS + s];
        float P = xi.x, E = xi.y, T1 = xi.z, T2 = xi.w;
        float Ta = (T1 + T2) * 0.5f;
        bool valid  = (T1 < 0.0f) && (T2 > 0.0f);
        float denom = valid ? (T2 - T1) : 1.0f;
        float ratio = valid ? (T1 + T2) / denom : 0.0f;
        ratio = fminf(fmaxf(ratio, -0.999999f), 0.999999f);
        float rP = 1.0f - acosf(ratio) / 3.1415f;
        if (T1 >= 0.0f) rP = 1.0f;
        if (T2 <= 0.0f) rP = 0.0f;
        float4 o;
        o.x = (1.0f - rP) * P;   // Ps
        o.y = rP * P;            // Pl
        o.z = Ta;
        o.w = E;
        sForc[t] = o;
    }
    if (tid == 0) sForc[NT] = make_float4(0.f, 0.f, 0.f, 0.f);  // prefetch pad
    __syncthreads();

    // ---- gates GEMV, coalesced ----
    // Warp w covers rows c*64 + 32w + [0,32).  One LDG.128 per lane covers
    // 4 consecutive rows x 8 quarter-rows: float4 idx = c*512 + w*256 + p*32 + lane.
    {
        const float4* fw4 = reinterpret_cast<const float4*>(fc_w);
        const float4  xq  = sXc4[lane & 7];
        const int     b0  = warp * 256 + lane;
        #pragma unroll 2
        for (int c = 0; c < 8; ++c) {
            float4 v[8];
            #pragma unroll
            for (int p = 0; p < 8; ++p) v[p] = fw4[c * 512 + b0 + p * 32];
            #pragma unroll
            for (int p = 0; p < 8; ++p) {
                float pr = v[p].x * xq.x + v[p].y * xq.y
                         + v[p].z * xq.z + v[p].w * xq.w;
                pr += __shfl_xor_sync(0xffffffffu, pr, 4);
                pr += __shfl_xor_sync(0xffffffffu, pr, 2);
                pr += __shfl_xor_sync(0xffffffffu, pr, 1);
                if ((lane & 7) == 0)
                    sW[c * 64 + warp * 32 + p * 4 + (lane >> 3)] = pr;
            }
        }
        // qb row (j = 513), computed by warp 1 (octet butterfly, all lanes active)
        if (warp == 1) {
            float4 v = fw4[513 * 8 + (lane & 7)];
            float pr = v.x * xq.x + v.y * xq.y + v.z * xq.z + v.w * xq.w;
            pr += __shfl_xor_sync(0xffffffffu, pr, 4);
            pr += __shfl_xor_sync(0xffffffffu, pr, 2);
            pr += __shfl_xor_sync(0xffffffffu, pr, 1);
            if (lane == 0)
                sQb = fmaxf(pr + fc_b[513], 0.0f) * (1.0f / 64.0f);
        }
    }
    __syncthreads();

    // ---- per-h activations (h = tid) ----
    const int h = tid;
    float wv[8];
    #pragma unroll
    for (int c = 0; c < 8; ++c) wv[c] = sW[c * 64 + h] + fc_b[c * NH + h];

    float gm   = expf(wv[0]) + 1.0f;
    float nge  = -2.0f * sigm(wv[1]);
    float go   = sigm(wv[2]);
    float gl   = expf(2.0f * wv[3]);
    float araw = wv[4];
    float gb   = sigm(wv[5]);
    float kb   = sigm(wv[6]) * 0.1f;
    float gi   = sigm(wv[7]);
    float kb1  = 1.0f - kb;

    // ---- softmax over 64 h across 2 warps ----
    __syncthreads();                         // sW reads done before overlay reuse
    float m = araw;
    #pragma unroll
    for (int o = 16; o; o >>= 1) m = fmaxf(m, __shfl_xor_sync(0xffffffffu, m, o));
    if (lane == 0) sMax[warp] = m;
    __syncthreads();
    m = fmaxf(sMax[0], sMax[1]);
    float e = expf(araw - m);
    float ssum = e;
    #pragma unroll
    for (int o = 16; o; o >>= 1) ssum += __shfl_xor_sync(0xffffffffu, ssum, o);
    if (lane == 0) sSum[warp] = ssum;
    __syncthreads();
    float ga = e / (sSum[0] + sSum[1]);

    float chc  = go * (1.0f - gb) * ga - ga;   // coeff of Hc in y
    float cg   = kb * ga;                      // coeff of g2 in y
    float gogb = go * gb;

    __syncthreads();                         // scratch reads done; sPart free

    // ---- sequential scan: prefetched, branch-free, unroll 2 ----
    float S0 = 0.0f, H0 = 0.0f, G0 = 0.0f;
    const int pbase = (warp << 3) + (lane & 7);
    float4 f = sForc[0];

    #pragma unroll 2
    for (int t = 0; t < NT; ++t) {
        float4 fn = sForc[t + 1];              // prefetch next step
        float mt  = fmaxf(f.z * gm, 0.0f);
        float Sm  = fminf(S0, mt);
        float At  = fmaf(f.w, nge, f.y * gi);  // Pl*gi - E*ge
        float H   = fmaxf(H0 + Sm + At, 0.0f);
        float Hc  = fminf(H, gl);
        float t1  = fmaf(-go, Hc, H);          // H - Hc*go
        float g2  = fmaf(Hc, gogb, G0);
        H0 = fminf(t1, gl);
        G0 = g2 * kb1;
        S0 = (S0 - Sm) + f.x;
        float y = H * ga;
        y = fmaf(Hc, chc, y);
        y = fmaf(g2, cg, y);
        y += __shfl_xor_sync(0xffffffffu, y, 16);
        y += __shfl_xor_sync(0xffffffffu, y, 8);
        sPart[t * PITCH + pbase] = y;          // collapsed same-addr STS
        f = fn;
    }

    __syncthreads();

    // ---- post-pass: sum 16 partials per t (+qb), write out ----
    const float qb = sQb;
    for (int t = tid; t < NT; t += 64) {
        const float* row = sPart + t * PITCH;
        float acc = qb;
        #pragma unroll
        for (int k = 0; k < 16; ++k) acc += row[k];
        out[t * NS + s] = acc;
    }
}

// ---------------------------------------------------------------------------
extern "C" void kernel_launch(void* const* d_in, const int* in_sizes, int n_in,
                              void* d_out, int out_size) {
    const float* x    = (const float*)d_in[0];   // [NT, NS, 4]
    const float* xc   = (const float*)d_in[1];   // [NS, NG]
    const float* fc_w = (const float*)d_in[2];   // [NW, NG]
    const float* fc_b = (const float*)d_in[3];   // [NW]
    float* out = (float*)d_out;                  // [NT, NS]

    waternet_kernel<<<NS, 64>>>(x, xc, fc_w, fc_b, out);
}

// round 7
// speedup vs baseline: 1.5351x; 1.0642x over previous
#include <cuda_runtime.h>
#include <math.h>

#define NT 365
#define NTP 368          // padded to 23 chunks of 16
#define NCHUNK 23
#define CH 16
#define BPITCH 65        // chunk-buffer row pitch (2-way max on reduce)
#define NS 1024
#define NH 64
#define NG 32
#define NW 514           // NH*8 + 2

__device__ __forceinline__ float sigm(float x) { return 1.0f / (1.0f + expf(-x)); }

// ---------------------------------------------------------------------------
// One block (64 threads = 2 warps) per site.
//  Prologue: stage forcing (+acos), coalesced gate GEMV, softmax.
//  Loop:     23 chunks x 16 steps. Per step: LDS.128 forcing + ~16 math +
//            1 conflict-free STS of the lane's own y. NO shuffles, NO
//            reduction in the step body -> only 1 var-lat producer per step.
//  Per chunk: 1 syncthreads + transpose-reduce (4 lanes/t sum 16 each,
//            2 intra-quad shfl) + predicated STG. Double-buffered.
// ---------------------------------------------------------------------------
__global__ void __launch_bounds__(64)
waternet_kernel(const float* __restrict__ x,
                const float* __restrict__ xc,
                const float* __restrict__ fc_w,
                const float* __restrict__ fc_b,
                float* __restrict__ out) {
    __shared__ float4 sForc[NTP];              // 5888 B
    __shared__ float  sBuf[2][CH * BPITCH];    // 8320 B  (per-lane y chunks)
    __shared__ float  sW[8 * NH];              // 2048 B
    __shared__ float4 sXc4[8];
    __shared__ float  sMax[2], sSum[2], sQb;

    const int tid  = threadIdx.x;
    const int warp = tid >> 5;
    const int lane = tid & 31;
    const int s    = blockIdx.x;

    // ---- stage xc ----
    if (tid < 8) sXc4[tid] = reinterpret_cast<const float4*>(xc + s * NG)[tid];

    // ---- stage forcing + rain/snow partition (pad tail with zeros) ----
    const float4* x4 = reinterpret_cast<const float4*>(x);
    for (int t = tid; t < NTP; t += 64) {
        float4 o = make_float4(0.f, 0.f, 0.f, 0.f);
        if (t < NT) {
            float4 xi = x4[t * NS + s];
            float P = xi.x, E = xi.y, T1 = xi.z, T2 = xi.w;
            float Ta = (T1 + T2) * 0.5f;
            bool valid  = (T1 < 0.0f) && (T2 > 0.0f);
            float denom = valid ? (T2 - T1) : 1.0f;
            float ratio = valid ? (T1 + T2) / denom : 0.0f;
            ratio = fminf(fmaxf(ratio, -0.999999f), 0.999999f);
            float rP = 1.0f - acosf(ratio) / 3.1415f;
            if (T1 >= 0.0f) rP = 1.0f;
            if (T2 <= 0.0f) rP = 0.0f;
            o.x = (1.0f - rP) * P;   // Ps
            o.y = rP * P;            // Pl
            o.z = Ta;
            o.w = E;
        }
        sForc[t] = o;
    }
    __syncthreads();

    // ---- gates GEMV, coalesced (1 LDG.128 = 4 consecutive rows' quarters) ----
    {
        const float4* fw4 = reinterpret_cast<const float4*>(fc_w);
        const float4  xq  = sXc4[lane & 7];
        const int     b0  = warp * 256 + lane;
        #pragma unroll 2
        for (int c = 0; c < 8; ++c) {
            float4 v[8];
            #pragma unroll
            for (int p = 0; p < 8; ++p) v[p] = fw4[c * 512 + b0 + p * 32];
            #pragma unroll
            for (int p = 0; p < 8; ++p) {
                float pr = v[p].x * xq.x + v[p].y * xq.y
                         + v[p].z * xq.z + v[p].w * xq.w;
                pr += __shfl_xor_sync(0xffffffffu, pr, 4);
                pr += __shfl_xor_sync(0xffffffffu, pr, 2);
                pr += __shfl_xor_sync(0xffffffffu, pr, 1);
                if ((lane & 7) == 0)
                    sW[c * 64 + warp * 32 + p * 4 + (lane >> 3)] = pr;
            }
        }
        if (warp == 1) {   // qb row (j = 513)
            float4 v = fw4[513 * 8 + (lane & 7)];
            float pr = v.x * xq.x + v.y * xq.y + v.z * xq.z + v.w * xq.w;
            pr += __shfl_xor_sync(0xffffffffu, pr, 4);
            pr += __shfl_xor_sync(0xffffffffu, pr, 2);
            pr += __shfl_xor_sync(0xffffffffu, pr, 1);
            if (lane == 0)
                sQb = fmaxf(pr + fc_b[513], 0.0f) * (1.0f / 64.0f);
        }
    }
    __syncthreads();

    // ---- per-h activations (h = tid) ----
    const int h = tid;
    float wv[8];
    #pragma unroll
    for (int c = 0; c < 8; ++c) wv[c] = sW[c * 64 + h] + fc_b[c * NH + h];

    float gm   = expf(wv[0]) + 1.0f;
    float nge  = -2.0f * sigm(wv[1]);
    float go   = sigm(wv[2]);
    float gl   = expf(2.0f * wv[3]);
    float araw = wv[4];
    float gb   = sigm(wv[5]);
    float kb   = sigm(wv[6]) * 0.1f;
    float gi   = sigm(wv[7]);
    float kb1  = 1.0f - kb;

    // ---- softmax over 64 h across 2 warps ----
    float m = araw;
    #pragma unroll
    for (int o = 16; o; o >>= 1) m = fmaxf(m, __shfl_xor_sync(0xffffffffu, m, o));
    if (lane == 0) sMax[warp] = m;
    __syncthreads();
    m = fmaxf(sMax[0], sMax[1]);
    float e = expf(araw - m);
    float ssum = e;
    #pragma unroll
    for (int o = 16; o; o >>= 1) ssum += __shfl_xor_sync(0xffffffffu, ssum, o);
    if (lane == 0) sSum[warp] = ssum;
    __syncthreads();
    float ga = e / (sSum[0] + sSum[1]);

    float chc  = go * (1.0f - gb) * ga - ga;   // coeff of Hc in y
    float cg   = kb * ga;                      // coeff of g2 in y
    float gogb = go * gb;
    const float qb = sQb;

    // reduction mapping: quad (4 lanes) per timestep
    const int rt = tid >> 2;        // 0..15  (local timestep)
    const int rq = tid & 3;         // quarter of the 64 lanes
    float* rrow = &sBuf[0][rt * BPITCH + rq * 16];
    const bool wlane = (rq == 0);

    // ---- sequential scan: chunked, shuffle-free body ----
    float S0 = 0.0f, H0 = 0.0f, G0 = 0.0f;

    for (int c = 0; c < NCHUNK; ++c) {
        float* buf = sBuf[c & 1];
        const float4* fp = sForc + c * CH;
        #pragma unroll
        for (int tt = 0; tt < CH; ++tt) {
            float4 f  = fp[tt];                    // broadcast LDS.128
            float mt  = fmaxf(f.z * gm, 0.0f);
            float Sm  = fminf(S0, mt);
            float At  = fmaf(f.w, nge, f.y * gi);  // Pl*gi - E*ge
            float H   = fmaxf(H0 + Sm + At, 0.0f);
            float Hc  = fminf(H, gl);
            float t1  = fmaf(-go, Hc, H);          // H - Hc*go
            float g2  = fmaf(Hc, gogb, G0);
            H0 = fminf(t1, gl);
            G0 = g2 * kb1;
            S0 = (S0 - Sm) + f.x;
            float y = H * ga;
            y = fmaf(Hc, chc, y);
            y = fmaf(g2, cg, y);
            buf[tt * BPITCH + tid] = y;            // conflict-free, no wbar
        }
        __syncthreads();                           // chunk writes visible
        // transpose-reduce chunk c: 4 lanes per t, 16 sums each
        {
            const float* rr = rrow + (c & 1) * (CH * BPITCH);
            float p = 0.0f;
            #pragma unroll
            for (int j = 0; j < 16; ++j) p += rr[j];
            p += __shfl_xor_sync(0xffffffffu, p, 1);
            p += __shfl_xor_sync(0xffffffffu, p, 2);
            int tg = c * CH + rt;
            if (wlane && tg < NT) out[tg * NS + s] = p + qb;
        }
        // barrier at next chunk's end orders these reads before buffer reuse
    }
}

// ---------------------------------------------------------------------------
extern "C" void kernel_launch(void* const* d_in, const int* in_sizes, int n_in,
                              void* d_out, int out_size) {
    const float* x    = (const float*)d_in[0];   // [NT, NS, 4]
    const float* xc   = (const float*)d_in[1];   // [NS, NG]
    const float* fc_w = (const float*)d_in[2];   // [NW, NG]
    const float* fc_b = (const float*)d_in[3];   // [NW]
    float* out = (float*)d_out;                  // [NT, NS]

    waternet_kernel<<<NS, 64>>>(x, xc, fc_w, fc_b, out);
}